// round 5
// baseline (speedup 1.0000x reference)
#include <cuda_runtime.h>
#include <cuda_fp16.h>
#include <cstdint>
#include <math.h>

#define BSZ  4
#define SEQ  2048
#define FDIM 256
#define MROWS (BSZ*SEQ)          /* 8192 */
#define ALPHA 0.2f
#define MASK_FILL -9000000000000000.0f
#define NSPLIT 16
#define PMW (SEQ/32)             /* 64 mask words per row */

/* ---------------- scratch (device globals) ------------------------------ */
__device__ __half   g_WhH[BSZ*FDIM*SEQ];     /* 4 MB Wh^T fp16 [b][o][tok] */
__device__ float2   g_w12[FDIM];             /* {W@a1, W@a2}               */
__device__ float    g_f1[MROWS];
__device__ float    g_f2[MROWS];
__device__ float2   g_f2c[MROWS];            /* {f2_j, C_j}                */
__device__ unsigned g_pmask[MROWS*PMW];      /* 2 MB packed mask bits      */
__device__ float    g_pm[NSPLIT][MROWS];
__device__ float    g_pd[NSPLIT][MROWS];

/* ======================= helpers ======================================== */
__device__ __forceinline__ float fexp(float x) {
    x = fmaxf(x, -87.0f);
    float y = fmaf(x, 1.4426950408889634f, 12582912.0f);
    int   n = __float_as_int(y) - 0x4B400000;
    float t = y - 12582912.0f;
    float f = fmaf(x, 1.4426950408889634f, -t);
    float p =          1.3333558e-3f;
    p = fmaf(p, f, 9.6181291e-3f);
    p = fmaf(p, f, 5.5504109e-2f);
    p = fmaf(p, f, 2.4022651e-1f);
    p = fmaf(p, f, 6.9314718e-1f);
    p = fmaf(p, f, 1.0f);
    return __uint_as_float(__float_as_int(p) + (n << 23));
}
__device__ __forceinline__ uint32_t smem_u32(const void* p) {
    uint32_t a;
    asm("{ .reg .u64 t; cvta.to.shared.u64 t, %1; cvt.u32.u64 %0, t; }"
        : "=r"(a) : "l"(p));
    return a;
}
#define STS128(a, r0, r1, r2, r3) \
    asm volatile("st.shared.v4.b32 [%0], {%1,%2,%3,%4};" \
                 :: "r"(a), "r"(r0), "r"(r1), "r"(r2), "r"(r3) : "memory")
__device__ __forceinline__ uint32_t lds32(uint32_t a) {
    uint32_t v;
    asm volatile("ld.shared.b32 %0, [%1];" : "=r"(v) : "r"(a));
    return v;
}
__device__ __forceinline__ void lds128(uint32_t a, uint32_t* r) {
    asm volatile("ld.shared.v4.b32 {%0,%1,%2,%3}, [%4];"
                 : "=r"(r[0]), "=r"(r[1]), "=r"(r[2]), "=r"(r[3]) : "r"(a));
}
__device__ __forceinline__ void mma16816(float* c, uint32_t a0, uint32_t a1,
                                         uint32_t a2, uint32_t a3,
                                         uint32_t b0, uint32_t b1) {
    asm volatile("mma.sync.aligned.m16n8k16.row.col.f32.f16.f16.f32 "
                 "{%0,%1,%2,%3},{%4,%5,%6,%7},{%8,%9},{%0,%1,%2,%3};"
                 : "+f"(c[0]), "+f"(c[1]), "+f"(c[2]), "+f"(c[3])
                 : "r"(a0), "r"(a1), "r"(a2), "r"(a3), "r"(b0), "r"(b1));
}
__device__ __forceinline__ uint32_t h2u(__half2 h) { return *(uint32_t*)&h; }

/* ============ kernel 0: w12 = W @ [a1,a2]  (warp per f-row) ============== */
__global__ void w12_kernel(const float* __restrict__ W, const float* __restrict__ a) {
    int f = blockIdx.x * 8 + (threadIdx.x >> 5);
    int lane = threadIdx.x & 31;
    const float* wr = &W[(size_t)f * FDIM];
    float s1 = 0.f, s2 = 0.f;
#pragma unroll
    for (int q = 0; q < 8; q++) {
        float w = wr[lane + q * 32];
        s1 += w * __ldg(&a[lane + q * 32]);
        s2 += w * __ldg(&a[FDIM + lane + q * 32]);
    }
#pragma unroll
    for (int off = 16; off; off >>= 1) {
        s1 += __shfl_xor_sync(0xffffffffu, s1, off);
        s2 += __shfl_xor_sync(0xffffffffu, s2, off);
    }
    if (!lane) g_w12[f] = make_float2(s1, s2);
}

/* ============ kernel 0b: f1,f2 = h @ w12  (warp per token) =============== */
__global__ void f12_kernel(const float* __restrict__ h) {
    int row  = blockIdx.x * 8 + (threadIdx.x >> 5);   /* global token */
    int lane = threadIdx.x & 31;
    const float* hr = &h[(size_t)row * FDIM];
    float s1 = 0.f, s2 = 0.f;
#pragma unroll
    for (int q = 0; q < 8; q++) {
        float hv = hr[lane + q * 32];
        float2 w = g_w12[lane + q * 32];
        s1 = fmaf(hv, w.x, s1);
        s2 = fmaf(hv, w.y, s2);
    }
#pragma unroll
    for (int off = 16; off; off >>= 1) {
        s1 += __shfl_xor_sync(0xffffffffu, s1, off);
        s2 += __shfl_xor_sync(0xffffffffu, s2, off);
    }
    if (!lane) { g_f1[row] = s1; g_f2[row] = s2; }
}

/* =================== kernel 1: Wh^T fp16 ================================= */
__global__ void gemm_wh(const float* __restrict__ A, const float* __restrict__ B) {
    const int BM = 64, BN = 64, BK = 32;
    __shared__ float As[BK][BM + 4];
    __shared__ float Bs[BK][BN];
    __shared__ float Ts[64][68];
    const int K = FDIM;
    int bm = blockIdx.x * BM, bn = blockIdx.y * BN;
    int tid = threadIdx.x;
    int tx = tid & 15, ty = tid >> 4;
    int ar = tid >> 3, ac = (tid & 7) * 4;
    int br = tid >> 4, bc = (tid & 15) * 4;
    float acc[4][4] = {};

    for (int k0 = 0; k0 < K; k0 += BK) {
#pragma unroll
        for (int r = 0; r < 2; r++) {
            int row = ar + 32 * r;
            float4 v = *(const float4*)&A[(size_t)(bm + row) * K + k0 + ac];
            As[ac + 0][row] = v.x; As[ac + 1][row] = v.y;
            As[ac + 2][row] = v.z; As[ac + 3][row] = v.w;
        }
#pragma unroll
        for (int r = 0; r < 2; r++) {
            int row = br + 16 * r;
            *(float4*)&Bs[row][bc] =
                *(const float4*)&B[(size_t)(k0 + row) * FDIM + bn + bc];
        }
        __syncthreads();
#pragma unroll
        for (int kk = 0; kk < BK; kk++) {
            float4 a = *(const float4*)&As[kk][ty * 4];
            float4 b = *(const float4*)&Bs[kk][tx * 4];
            float av[4] = {a.x, a.y, a.z, a.w};
            float bv[4] = {b.x, b.y, b.z, b.w};
#pragma unroll
            for (int i = 0; i < 4; i++)
#pragma unroll
                for (int j = 0; j < 4; j++)
                    acc[i][j] += av[i] * bv[j];
        }
        __syncthreads();
    }
#pragma unroll
    for (int i = 0; i < 4; i++)
#pragma unroll
        for (int j = 0; j < 4; j++)
            Ts[tx * 4 + j][ty * 4 + i] = acc[i][j];
    __syncthreads();
    int b = bm / SEQ, n0 = bm % SEQ;
    int orow = tid >> 2, cs = (tid & 3) * 16;
#pragma unroll
    for (int q = 0; q < 4; q++) {
        float4 v = *(float4*)&Ts[orow][cs + 4 * q];
        size_t off = ((size_t)b * FDIM + bn + orow) * SEQ + n0 + cs + 4 * q;
        uint2 pk;
        pk.x = h2u(__floats2half2_rn(v.x, v.y));
        pk.y = h2u(__floats2half2_rn(v.z, v.w));
        *(uint2*)&g_WhH[off] = pk;
    }
}

/* ==== kernel 3a: partial online softmax (4 j per thread) + mask pack ==== */
__global__ void stats_partial(const int* __restrict__ mask) {
    int b  = blockIdx.z;
    int lane = threadIdx.x & 31, w = threadIdx.x >> 5;
    int jb = blockIdx.x * 512 + w * 128;
    int i0 = blockIdx.y * (SEQ / NSPLIT);

    float f2v[4], m[4], den[4];
#pragma unroll
    for (int q = 0; q < 4; q++) {
        f2v[q] = g_f2[b * SEQ + jb + q * 32 + lane];
        m[q] = MASK_FILL; den[q] = 0.f;
    }
    const int* mp = mask + ((size_t)b * SEQ + i0) * SEQ + jb + lane;
    unsigned* pw = &g_pmask[((size_t)b * SEQ + i0) * PMW + (jb >> 5)];
    const float* f1p = &g_f1[b * SEQ + i0];

    for (int it = 0; it < SEQ / NSPLIT; it += 2) {
        int mv[2][4]; float fv[2];
#pragma unroll
        for (int u = 0; u < 2; u++) {
            const int* mr = mp + (size_t)(it + u) * SEQ;
#pragma unroll
            for (int q = 0; q < 4; q++) mv[u][q] = mr[q * 32];
            fv[u] = f1p[it + u];
        }
#pragma unroll
        for (int u = 0; u < 2; u++) {
            unsigned* pr = pw + (size_t)(it + u) * PMW;
#pragma unroll
            for (int q = 0; q < 4; q++) {
                unsigned bal = __ballot_sync(0xffffffffu, mv[u][q] > 0);
                if (lane == 0) pr[q] = bal;
                float e = fv[u] + f2v[q];
                float v = (mv[u][q] > 0) ? (e >= 0.f ? e : ALPHA * e) : MASK_FILL;
                if (v > m[q]) { den[q] = den[q] * fexp(m[q] - v) + 1.f; m[q] = v; }
                else          { den[q] += fexp(v - m[q]); }
            }
        }
    }
#pragma unroll
    for (int q = 0; q < 4; q++) {
        g_pm[blockIdx.y][b * SEQ + jb + q * 32 + lane] = m[q];
        g_pd[blockIdx.y][b * SEQ + jb + q * 32 + lane] = den[q];
    }
}

/* ============ kernel 3b: combine partials -> {f2, C} float2 ============== */
__global__ void stats_combine() {
    int idx = blockIdx.x * 256 + threadIdx.x;
    float m = MASK_FILL;
#pragma unroll
    for (int s = 0; s < NSPLIT; s++) m = fmaxf(m, g_pm[s][idx]);
    float den = 0.f;
#pragma unroll
    for (int s = 0; s < NSPLIT; s++) den += g_pd[s][idx] * fexp(g_pm[s][idx] - m);
    g_f2c[idx] = make_float2(g_f2[idx], m + __logf(den));
}

/* ======= kernel 4: h' = P @ Wh, 64x128 tile, 128 thr, occ>=2 ============ */
#define SM_PS   256                        /* 2 x 4 KB  A frag-permuted   */
#define SM_WHS  (SM_PS + 8192)             /* 2 x 18432 B [n][k pad 72h]  */
#define ATTN_SMEM (SM_WHS + 36864)         /* 45312 bytes (static)        */

__global__ void __launch_bounds__(128, 3) attn_mma(float* __restrict__ out) {
    __shared__ char smem[ATTN_SMEM];
    uint32_t sb = smem_u32(smem);
    float* f1s = (float*)smem;             /* 64 floats, dead after read  */

    int tid = threadIdx.x, lane = tid & 31, wid = tid >> 5;
    int b = blockIdx.z, i0 = blockIdx.x * 64, o0 = blockIdx.y * 128;

    if (tid < 64) f1s[tid] = g_f1[b * SEQ + i0 + tid];
    __syncthreads();

    /* builder: mt_g 0..3, bg 0..7, bt 0..3 -> rows r0, r0+8 */
    int mt_g = tid >> 5, bg = (tid >> 2) & 7, bt = tid & 3;
    int r0 = mt_g * 16 + bg;
    const unsigned* pm0 = &g_pmask[((size_t)(b * SEQ) + i0 + r0) * PMW];
    const unsigned* pm1 = pm0 + 8 * PMW;
    float f1a = f1s[r0], f1b = f1s[r0 + 8];
    const float2* f2cb = &g_f2c[b * SEQ];
    __syncthreads();                        /* f1s reads done before reuse */

    /* B loader: thread = n-row */
    const int4* wsrc = (const int4*)(g_WhH + ((size_t)(b * FDIM) + o0 + tid) * SEQ);

    /* mma: warp grid 2m x 2n, warp tile 32x64 */
    int wm = wid >> 1, wn = wid & 1, fg = lane >> 2, ft = lane & 3;
    float acc[2][8][4];
#pragma unroll
    for (int i = 0; i < 2; i++)
#pragma unroll
        for (int j = 0; j < 8; j++)
#pragma unroll
            for (int k = 0; k < 4; k++) acc[i][j][k] = 0.f;

    for (int s = 0; s < 64; s++) {
        int buf = s & 1, k0 = s * 32;
        uint32_t psb = sb + SM_PS  + (uint32_t)buf * 4096u;
        uint32_t whb = sb + SM_WHS + (uint32_t)buf * 18432u;

        /* prefetch gmem */
        int4 v0 = __ldg(wsrc + s * 4),     v1 = __ldg(wsrc + s * 4 + 1);
        int4 v2 = __ldg(wsrc + s * 4 + 2), v3 = __ldg(wsrc + s * 4 + 3);
        unsigned w0 = __ldg(pm0 + s), w1 = __ldg(pm1 + s);

        /* build P tile in frag-permuted layout */
#pragma unroll
        for (int ks = 0; ks < 2; ks++) {
            int jb = k0 + ks * 16;
            float4 F0 = __ldg((const float4*)&f2cb[jb + 2 * bt]);
            float4 F1 = __ldg((const float4*)&f2cb[jb + 2 * bt + 8]);
            int sh = ks * 16;
            float e, v;
            e = f1a + F0.x; v = e >= 0.f ? e : ALPHA * e;
            float pa0 = ((w0 >> (sh + 2*bt))     & 1u) ? fexp(v - F0.y) : 0.f;
            e = f1a + F0.z; v = e >= 0.f ? e : ALPHA * e;
            float pa1 = ((w0 >> (sh + 2*bt + 1)) & 1u) ? fexp(v - F0.w) : 0.f;
            e = f1b + F0.x; v = e >= 0.f ? e : ALPHA * e;
            float pb0 = ((w1 >> (sh + 2*bt))     & 1u) ? fexp(v - F0.y) : 0.f;
            e = f1b + F0.z; v = e >= 0.f ? e : ALPHA * e;
            float pb1 = ((w1 >> (sh + 2*bt + 1)) & 1u) ? fexp(v - F0.w) : 0.f;
            e = f1a + F1.x; v = e >= 0.f ? e : ALPHA * e;
            float pa2 = ((w0 >> (sh + 2*bt + 8)) & 1u) ? fexp(v - F1.y) : 0.f;
            e = f1a + F1.z; v = e >= 0.f ? e : ALPHA * e;
            float pa3 = ((w0 >> (sh + 2*bt + 9)) & 1u) ? fexp(v - F1.w) : 0.f;
            e = f1b + F1.x; v = e >= 0.f ? e : ALPHA * e;
            float pb2 = ((w1 >> (sh + 2*bt + 8)) & 1u) ? fexp(v - F1.y) : 0.f;
            e = f1b + F1.z; v = e >= 0.f ? e : ALPHA * e;
            float pb3 = ((w1 >> (sh + 2*bt + 9)) & 1u) ? fexp(v - F1.w) : 0.f;

            uint32_t h0 = h2u(__floats2half2_rn(pa0, pa1));
            uint32_t h1 = h2u(__floats2half2_rn(pb0, pb1));
            uint32_t h2_ = h2u(__floats2half2_rn(pa2, pa3));
            uint32_t h3 = h2u(__floats2half2_rn(pb2, pb3));
            uint32_t set = (uint32_t)(mt_g * 64 + bg * 8 + bt * 2 + ks);
            STS128(psb + ((set * 16u) ^ ((uint32_t)bg << 4)), h0, h1, h2_, h3);
        }
        /* stage B: row tid, pad 72 halfs (144B, conflict-free) */
        {
            char* wd = smem + SM_WHS + buf * 18432 + tid * 144;
            *(int4*)wd = v0; *(int4*)(wd + 16) = v1;
            *(int4*)(wd + 32) = v2; *(int4*)(wd + 48) = v3;
        }
        __syncthreads();

        /* mma phase */
#pragma unroll
        for (int ks = 0; ks < 2; ks++) {
            uint32_t afr[2][4];
#pragma unroll
            for (int mt = 0; mt < 2; mt++) {
                uint32_t set = (uint32_t)((wm * 2 + mt) * 64 + fg * 8 + ft * 2 + ks);
                lds128(psb + ((set * 16u) ^ ((uint32_t)fg << 4)), afr[mt]);
            }
#pragma unroll
            for (int nt = 0; nt < 8; nt++) {
                uint32_t bad = whb +
                    (uint32_t)((wn * 64 + nt * 8 + fg) * 144 + ks * 32 + 4 * ft);
                uint32_t b0 = lds32(bad), b1 = lds32(bad + 16);
#pragma unroll
                for (int mt = 0; mt < 2; mt++)
                    mma16816(acc[mt][nt], afr[mt][0], afr[mt][1], afr[mt][2],
                             afr[mt][3], b0, b1);
            }
        }
    }

    /* epilogue: ELU + store */
#pragma unroll
    for (int mt = 0; mt < 2; mt++) {
        int ia = i0 + wm * 32 + mt * 16 + fg;
#pragma unroll
        for (int nt = 0; nt < 8; nt++) {
            int oc = o0 + wn * 64 + nt * 8 + 2 * ft;
            float* c = acc[mt][nt];
            float2 u; float x;
            x = c[0]; u.x = x > 0.f ? x : fexp(x) - 1.f;
            x = c[1]; u.y = x > 0.f ? x : fexp(x) - 1.f;
            *(float2*)&out[((size_t)(b * SEQ) + ia) * FDIM + oc] = u;
            x = c[2]; u.x = x > 0.f ? x : fexp(x) - 1.f;
            x = c[3]; u.y = x > 0.f ? x : fexp(x) - 1.f;
            *(float2*)&out[((size_t)(b * SEQ) + ia + 8) * FDIM + oc] = u;
        }
    }
}

/* ============================== launcher ================================= */
extern "C" void kernel_launch(void* const* d_in, const int* in_sizes, int n_in,
                              void* d_out, int out_size) {
    const float* h = nullptr; const int* mask = nullptr;
    const float* W = nullptr; const float* a = nullptr;
    for (int t = 0; t < n_in; t++) {
        if      (in_sizes[t] == BSZ * SEQ * FDIM) h    = (const float*)d_in[t];
        else if (in_sizes[t] == BSZ * SEQ * SEQ)  mask = (const int*)  d_in[t];
        else if (in_sizes[t] == FDIM * FDIM)      W    = (const float*)d_in[t];
        else if (in_sizes[t] == 2 * FDIM)         a    = (const float*)d_in[t];
    }
    float* out = (float*)d_out;

    w12_kernel<<<FDIM / 8, 256>>>(W, a);
    f12_kernel<<<MROWS / 8, 256>>>(h);

    dim3 g1(MROWS / 64, FDIM / 64);
    gemm_wh<<<g1, 256>>>(h, W);

    dim3 g3(SEQ / 512, NSPLIT, BSZ);
    stats_partial<<<g3, 128>>>(mask);

    stats_combine<<<MROWS / 256, 256>>>();

    dim3 g4(SEQ / 64, FDIM / 128, BSZ);
    attn_mma<<<g4, 128>>>(out);
}